// round 9
// baseline (speedup 1.0000x reference)
#include <cuda_runtime.h>
#include <cuda_bf16.h>
#include <cstdint>

#define EMBED 768
#define OUTD  1024
#define HEADS 8
#define HD    128
#define MAXN  10000
#define MAXE  160000
#define MAXET (MAXN + MAXE)
#define PADN  10112            // 79 * 128

// ---------------- scratch ----------------
__device__ float    g_xs[MAXN * OUTD];
__device__ float    g_h[MAXN * OUTD];        // only rows text/image are written
__device__ float    g_asrc[MAXN * HEADS];
__device__ float    g_adst[MAXN * HEADS];
__device__ float    g_scal[16];              // [0]=sum(ea), [1..8]=k[h]
__device__ float    g_pool[OUTD];
// CSR by dst
__device__ int      g_deg[MAXN];
__device__ int      g_off[MAXN + 1];
__device__ int      g_cur[MAXN];
__device__ unsigned g_csr[MAXET];            // (edge_id << 14) | src
// bf16-split copies for tensor-core GEMM
__device__ __nv_bfloat16 g_Ahi[(size_t)PADN * EMBED];
__device__ __nv_bfloat16 g_Alo[(size_t)PADN * EMBED];
__device__ __nv_bfloat16 g_Whi[(size_t)OUTD * EMBED];   // W^T [n][k]
__device__ __nv_bfloat16 g_Wlo[(size_t)OUTD * EMBED];

// ---------------- PTX helpers ----------------
__device__ __forceinline__ uint32_t smem_u32(const void* p) {
    uint32_t a;
    asm("{ .reg .u64 t; cvta.to.shared.u64 t, %1; cvt.u32.u64 %0, t; }" : "=r"(a) : "l"(p));
    return a;
}
__device__ __forceinline__ void cp16(uint32_t s, const void* g) {
    asm volatile("cp.async.cg.shared.global [%0], [%1], 16;" :: "r"(s), "l"(g));
}
__device__ __forceinline__ void cp_commit() {
    asm volatile("cp.async.commit_group;" ::: "memory");
}
template <int N>
__device__ __forceinline__ void cp_wait() {
    asm volatile("cp.async.wait_group %0;" :: "n"(N) : "memory");
}
__device__ __forceinline__ void ldsm4(uint32_t& r0, uint32_t& r1, uint32_t& r2, uint32_t& r3,
                                      uint32_t addr) {
    asm volatile("ldmatrix.sync.aligned.m8n8.x4.shared.b16 {%0,%1,%2,%3}, [%4];"
                 : "=r"(r0), "=r"(r1), "=r"(r2), "=r"(r3) : "r"(addr));
}
__device__ __forceinline__ void mma16816(float* d, const uint32_t* a, const uint32_t* b) {
    asm volatile(
        "mma.sync.aligned.m16n8k16.row.col.f32.bf16.bf16.f32 "
        "{%0,%1,%2,%3}, {%4,%5,%6,%7}, {%8,%9}, {%0,%1,%2,%3};"
        : "+f"(d[0]), "+f"(d[1]), "+f"(d[2]), "+f"(d[3])
        : "r"(a[0]), "r"(a[1]), "r"(a[2]), "r"(a[3]), "r"(b[0]), "r"(b[1]));
}

__device__ __forceinline__ uint32_t sw_off(int row, int c) {
    return (uint32_t)(row * 64 + ((c ^ ((row >> 1) & 3)) << 4));
}

// ---------------- K0a: split x into bf16 hi/lo (float4 vectorized) ----------------
__global__ void k_cvtA(const float4* __restrict__ x, int N) {
    int i = blockIdx.x * blockDim.x + threadIdx.x;
    if (i >= PADN * (EMBED / 4)) return;
    int row = i / (EMBED / 4);
    float4 v = (row < N) ? x[i] : make_float4(0.f, 0.f, 0.f, 0.f);
    __nv_bfloat16 h0 = __float2bfloat16(v.x), h1 = __float2bfloat16(v.y);
    __nv_bfloat16 h2 = __float2bfloat16(v.z), h3 = __float2bfloat16(v.w);
    __nv_bfloat162* hi = (__nv_bfloat162*)&g_Ahi[(size_t)i * 4];
    __nv_bfloat162* lo = (__nv_bfloat162*)&g_Alo[(size_t)i * 4];
    hi[0] = __nv_bfloat162(h0, h1);
    hi[1] = __nv_bfloat162(h2, h3);
    lo[0] = __nv_bfloat162(__float2bfloat16(v.x - __bfloat162float(h0)),
                           __float2bfloat16(v.y - __bfloat162float(h1)));
    lo[1] = __nv_bfloat162(__float2bfloat16(v.z - __bfloat162float(h2)),
                           __float2bfloat16(v.w - __bfloat162float(h3)));
}

// ---------------- K0b: W^T split via smem tile transpose (coalesced both ways) ----------------
__global__ __launch_bounds__(256)
void k_cvtW(const float* __restrict__ W) {
    __shared__ float tile[32][33];
    const int k0 = blockIdx.y * 32;     // over EMBED (24 blocks)
    const int n0 = blockIdx.x * 32;     // over OUTD  (32 blocks)
    const int tx = threadIdx.x & 31, ty = threadIdx.x >> 5;   // 32 x 8
    #pragma unroll
    for (int i = 0; i < 32; i += 8)
        tile[ty + i][tx] = W[(size_t)(k0 + ty + i) * OUTD + n0 + tx];
    __syncthreads();
    #pragma unroll
    for (int i = 0; i < 32; i += 8) {
        float v = tile[tx][ty + i];     // (k = k0+tx, n = n0+ty+i)
        __nv_bfloat16 hi = __float2bfloat16(v);
        __nv_bfloat16 lo = __float2bfloat16(v - __bfloat162float(hi));
        g_Whi[(size_t)(n0 + ty + i) * EMBED + k0 + tx] = hi;
        g_Wlo[(size_t)(n0 + ty + i) * EMBED + k0 + tx] = lo;
    }
}

// ---------------- K2: HMMA bf16-split GEMM + fused attention logits ----------------
#define KCH    32
#define NCHUNK (EMBED / KCH)      // 24
#define TILEB  (128 * 64)
#define STAGEB (4 * TILEB)
#define NSTAGE 3
#define SMEM_GEMM (NSTAGE * STAGEB)

__global__ __launch_bounds__(256, 2)
void k_gemm_mma(int M, const float* __restrict__ att_src,
                const float* __restrict__ att_dst) {
    extern __shared__ char smem[];
    const uint32_t sb = smem_u32(smem);
    const int tid = threadIdx.x;
    const int wid = tid >> 5, lane = tid & 31;
    const int warp_m = wid & 3;
    const int warp_n = wid >> 2;
    const int rowBase = blockIdx.y * 128;
    const int colBase = blockIdx.x * 128;
    const int head = colBase >> 7;

    const __nv_bfloat16* src[4] = {
        g_Ahi + (size_t)rowBase * EMBED,
        g_Alo + (size_t)rowBase * EMBED,
        g_Whi + (size_t)colBase * EMBED,
        g_Wlo + (size_t)colBase * EMBED };

    const int chunk0 = tid * 2;
    const int row0 = chunk0 >> 2, cc0 = chunk0 & 3;
    const int row1 = (chunk0 + 1) >> 2, cc1 = (chunk0 + 1) & 3;
    const uint32_t so0 = sw_off(row0, cc0);
    const uint32_t so1 = sw_off(row1, cc1);

    auto stage_load = [&](int c, int s) {
        const uint32_t base = sb + s * STAGEB;
        const int k0 = c * KCH;
        #pragma unroll
        for (int t = 0; t < 4; t++) {
            const __nv_bfloat16* g = src[t] + k0;
            cp16(base + t * TILEB + so0, g + (size_t)row0 * EMBED + cc0 * 8);
            cp16(base + t * TILEB + so1, g + (size_t)row1 * EMBED + cc1 * 8);
        }
        cp_commit();
    };

    stage_load(0, 0);
    stage_load(1, 1);

    float acc[2][8][4];
    #pragma unroll
    for (int mb = 0; mb < 2; mb++)
        #pragma unroll
        for (int nb = 0; nb < 8; nb++)
            #pragma unroll
            for (int j = 0; j < 4; j++) acc[mb][nb][j] = 0.f;

    const int l_tile = lane >> 3, l_rin = lane & 7;

    for (int c = 0; c < NCHUNK; c++) {
        if (c + 1 < NCHUNK) cp_wait<1>(); else cp_wait<0>();
        __syncthreads();
        if (c + 2 < NCHUNK) stage_load(c + 2, (c + 2) % NSTAGE);

        const uint32_t base = sb + (c % NSTAGE) * STAGEB;
        #pragma unroll
        for (int ks = 0; ks < 2; ks++) {
            uint32_t a[2][2][4];
            uint32_t b[2][8][2];
            #pragma unroll
            for (int v = 0; v < 2; v++)
                #pragma unroll
                for (int mb = 0; mb < 2; mb++) {
                    int r = warp_m * 32 + mb * 16 + ((l_tile & 1) << 3) + l_rin;
                    int cch = ks * 2 + (l_tile >> 1);
                    ldsm4(a[v][mb][0], a[v][mb][1], a[v][mb][2], a[v][mb][3],
                          base + v * TILEB + sw_off(r, cch));
                }
            #pragma unroll
            for (int v = 0; v < 2; v++)
                #pragma unroll
                for (int p = 0; p < 4; p++) {
                    int r = warp_n * 64 + p * 16 + ((l_tile >> 1) << 3) + l_rin;
                    int cch = ks * 2 + (l_tile & 1);
                    ldsm4(b[v][p * 2][0], b[v][p * 2][1],
                          b[v][p * 2 + 1][0], b[v][p * 2 + 1][1],
                          base + (2 + v) * TILEB + sw_off(r, cch));
                }
            #pragma unroll
            for (int mb = 0; mb < 2; mb++)
                #pragma unroll
                for (int nb = 0; nb < 8; nb++) {
                    mma16816(acc[mb][nb], a[0][mb], b[0][nb]);
                    mma16816(acc[mb][nb], a[0][mb], b[1][nb]);
                    mma16816(acc[mb][nb], a[1][mb], b[0][nb]);
                }
        }
        // no trailing sync: next iteration's top __syncthreads (after cp_wait)
        // orders all warps' compute(c) before any warp overwrites stage (c+3)%3.
    }

    const int tr = lane >> 2, tc = (lane & 3) * 2;

    float as[16], ad[16];
    #pragma unroll
    for (int nb = 0; nb < 8; nb++)
        #pragma unroll
        for (int j = 0; j < 2; j++) {
            int col = warp_n * 64 + nb * 8 + tc + j;
            as[nb * 2 + j] = att_src[head * HD + col];
            ad[nb * 2 + j] = att_dst[head * HD + col];
        }

    #pragma unroll
    for (int mb = 0; mb < 2; mb++) {
        #pragma unroll
        for (int half = 0; half < 2; half++) {
            int row = rowBase + warp_m * 32 + mb * 16 + half * 8 + tr;
            float ps = 0.f, pd = 0.f;
            #pragma unroll
            for (int nb = 0; nb < 8; nb++)
                #pragma unroll
                for (int j = 0; j < 2; j++) {
                    float v = acc[mb][nb][half * 2 + j];
                    ps += v * as[nb * 2 + j];
                    pd += v * ad[nb * 2 + j];
                }
            #pragma unroll
            for (int o = 1; o < 4; o <<= 1) {
                ps += __shfl_xor_sync(0xffffffffu, ps, o);
                pd += __shfl_xor_sync(0xffffffffu, pd, o);
            }
            if (row < M) {
                if ((lane & 3) == 0) {
                    atomicAdd(&g_asrc[row * HEADS + head], ps);
                    atomicAdd(&g_adst[row * HEADS + head], pd);
                }
                float* dst = &g_xs[(size_t)row * OUTD + colBase + warp_n * 64 + tc];
                #pragma unroll
                for (int nb = 0; nb < 8; nb++) {
                    float2 v = make_float2(acc[mb][nb][half * 2], acc[mb][nb][half * 2 + 1]);
                    *(float2*)(dst + nb * 8) = v;
                }
            }
        }
    }
}

// ---------------- K1a: parallel sum of ea ----------------
__global__ void k_easum(const float* __restrict__ ea, int E) {
    __shared__ float sh[256];
    float s = 0.f;
    for (int i = blockIdx.x * 256 + threadIdx.x; i < E; i += gridDim.x * 256) s += ea[i];
    sh[threadIdx.x] = s; __syncthreads();
    for (int o = 128; o; o >>= 1) {
        if (threadIdx.x < o) sh[threadIdx.x] += sh[threadIdx.x + o];
        __syncthreads();
    }
    if (threadIdx.x == 0) atomicAdd(&g_scal[0], sh[0]);
}

// ---------------- K1b: per-head edge coefficient k[h] ----------------
__global__ void k_kcoef(const float* __restrict__ Wedge,
                        const float* __restrict__ att_edge) {
    int wid = threadIdx.x >> 5, lane = threadIdx.x & 31;
    float s = 0.f;
    for (int c = lane; c < HD; c += 32)
        s += Wedge[wid * HD + c] * att_edge[wid * HD + c];
    #pragma unroll
    for (int o = 16; o; o >>= 1) s += __shfl_down_sync(0xffffffffu, s, o);
    if (lane == 0) g_scal[1 + wid] = s;
}

// ---------------- CSR build ----------------
__global__ void k_count(const int* __restrict__ ei, int E) {
    int e = blockIdx.x * blockDim.x + threadIdx.x;
    if (e < E) atomicAdd(&g_deg[ei[E + e]], 1);
}

__global__ __launch_bounds__(1024)
void k_scan(int N) {
    __shared__ int sh[1024];
    int t = threadIdx.x;
    int chunk = (N + 1023) / 1024;
    int s0 = min(t * chunk, N), s1 = min(s0 + chunk, N);
    int sum = 0;
    for (int n = s0; n < s1; n++) sum += g_deg[n] + 1;
    sh[t] = sum; __syncthreads();
    for (int o = 1; o < 1024; o <<= 1) {
        int v = (t >= o) ? sh[t - o] : 0;
        __syncthreads();
        sh[t] += v;
        __syncthreads();
    }
    int run = (t == 0) ? 0 : sh[t - 1];
    for (int n = s0; n < s1; n++) {
        g_off[n] = run;
        g_cur[n] = run;
        run += g_deg[n] + 1;
    }
    if (t == 1023) g_off[N] = sh[1023];
}

__global__ void k_fill(const int* __restrict__ ei, int E, int N) {
    int t = blockIdx.x * blockDim.x + threadIdx.x;
    if (t >= E + N) return;
    int d, s;
    if (t < E) { d = ei[E + t]; s = ei[t]; }
    else       { d = s = t - E; }
    int pos = atomicAdd(&g_cur[d], 1);
    g_csr[pos] = ((unsigned)t << 14) | (unsigned)s;
}

// ---------------- K6: CSR agg with inline softmax + fused mean-pool ----------------
__global__ __launch_bounds__(256)
void k_agg(int N, int E, const float* __restrict__ ea,
           const int* __restrict__ tip, const int* __restrict__ iip) {
    __shared__ float spool[OUTD];
    const int tid = threadIdx.x;
    for (int j = tid; j < OUTD; j += 256) spool[j] = 0.f;
    __syncthreads();

    int gw = (blockIdx.x * 256 + tid) >> 5;
    int lane = tid & 31;
    if (gw < N) {
        const int st = g_off[gw], en = g_off[gw + 1];

        // per-lane head state (lanes 0-7 active for softmax math)
        float adst_h = 0.f, kh = 0.f;
        if (lane < HEADS) {
            adst_h = g_adst[gw * HEADS + lane];
            kh = g_scal[1 + lane];
        }
        const float meanea = g_scal[0] / (float)E;

        float4 acc[HEADS];
        float dsum[HEADS];
        #pragma unroll
        for (int h = 0; h < HEADS; h++) {
            acc[h] = make_float4(0.f, 0.f, 0.f, 0.f);
            dsum[h] = 0.f;
        }

        for (int i = st; i < en; i++) {
            unsigned p = g_csr[i];
            int e = p >> 14, s = p & 0x3FFF;
            float w = 0.f;
            if (lane < HEADS) {
                float av = (e < E) ? ea[e] : meanea;
                float a = g_asrc[s * HEADS + lane] + adst_h + av * kh;
                a = (a >= 0.f) ? a : 0.2f * a;
                w = __expf(a);
            }
            const float4* row = (const float4*)&g_xs[(size_t)s * OUTD];
            #pragma unroll
            for (int h = 0; h < HEADS; h++) {
                float wh = __shfl_sync(0xffffffffu, w, h);
                float4 v = row[h * 32 + lane];
                dsum[h] += wh;
                acc[h].x += wh * v.x;
                acc[h].y += wh * v.y;
                acc[h].z += wh * v.z;
                acc[h].w += wh * v.w;
            }
        }
        #pragma unroll
        for (int h = 0; h < HEADS; h++) {
            float inv = 1.f / dsum[h];
            acc[h].x *= inv; acc[h].y *= inv; acc[h].z *= inv; acc[h].w *= inv;
        }

        #pragma unroll
        for (int h = 0; h < HEADS; h++) {
            float* sp = &spool[h * HD + lane * 4];
            atomicAdd(sp + 0, acc[h].x);
            atomicAdd(sp + 1, acc[h].y);
            atomicAdd(sp + 2, acc[h].z);
            atomicAdd(sp + 3, acc[h].w);
        }

        int t = tip[0], im = iip[0];
        if (gw == t || gw == im) {
            float4* out = (float4*)&g_h[(size_t)gw * OUTD];
            #pragma unroll
            for (int h = 0; h < HEADS; h++) out[h * 32 + lane] = acc[h];
        }
    }
    __syncthreads();
    for (int j = tid; j < OUTD; j += 256) atomicAdd(&g_pool[j], spool[j]);
}

// ---------------- K8: fused vector + classifier ----------------
__global__ void k_clf(const float* __restrict__ bias,
                      const int* __restrict__ tip, const int* __restrict__ iip,
                      const float* __restrict__ clfW, const float* __restrict__ clfb,
                      int N, float* __restrict__ out) {
    __shared__ float s0[256], s1[256];
    int t = threadIdx.x;
    int ti = tip[0], im = iip[0];
    float a0 = 0.f, a1 = 0.f;
    for (int j = t; j < 3 * OUTD; j += 256) {
        int jj = j & (OUTD - 1);
        int seg = j >> 10;
        float b = bias[jj];
        float f;
        if (seg == 0)      f = g_pool[jj] / (float)N + b;
        else if (seg == 1) f = g_h[(size_t)ti * OUTD + jj] + b;
        else               f = g_h[(size_t)im * OUTD + jj] + b;
        a0 += f * clfW[2 * j];
        a1 += f * clfW[2 * j + 1];
    }
    s0[t] = a0; s1[t] = a1; __syncthreads();
    for (int o = 128; o; o >>= 1) {
        if (t < o) { s0[t] += s0[t + o]; s1[t] += s1[t + o]; }
        __syncthreads();
    }
    if (t == 0) {
        out[0] = s0[0] + clfb[0];
        out[1] = s1[0] + clfb[1];
    }
}

// ---------------- launch ----------------
extern "C" void kernel_launch(void* const* d_in, const int* in_sizes, int n_in,
                              void* d_out, int out_size) {
    const float* x        = (const float*)d_in[0];
    const int*   ei       = (const int*)  d_in[1];
    const float* ea       = (const float*)d_in[2];
    const int*   tip      = (const int*)  d_in[3];
    const int*   iip      = (const int*)  d_in[4];
    const float* W        = (const float*)d_in[5];
    const float* att_src  = (const float*)d_in[6];
    const float* att_dst  = (const float*)d_in[7];
    const float* Wedge    = (const float*)d_in[8];
    const float* att_edge = (const float*)d_in[9];
    const float* bias     = (const float*)d_in[10];
    const float* clfW     = (const float*)d_in[11];
    const float* clfb     = (const float*)d_in[12];
    float* out = (float*)d_out;

    int N  = in_sizes[0] / EMBED;
    int E  = in_sizes[1] / 2;
    int ET = E + N;

    static cudaStream_t s1, s2;
    static cudaEvent_t evFork, evCSR, evW;
    static int inited = 0;
    if (!inited) {
        cudaStreamCreateWithFlags(&s1, cudaStreamNonBlocking);
        cudaStreamCreateWithFlags(&s2, cudaStreamNonBlocking);
        cudaEventCreateWithFlags(&evFork, cudaEventDisableTiming);
        cudaEventCreateWithFlags(&evCSR,  cudaEventDisableTiming);
        cudaEventCreateWithFlags(&evW,    cudaEventDisableTiming);
        cudaFuncSetAttribute(k_gemm_mma, cudaFuncAttributeMaxDynamicSharedMemorySize, SMEM_GEMM);
        inited = 1;
    }

    void *p_pool, *p_deg, *p_scal, *p_asrc, *p_adst;
    cudaGetSymbolAddress(&p_pool,  g_pool);
    cudaGetSymbolAddress(&p_deg,   g_deg);
    cudaGetSymbolAddress(&p_scal,  g_scal);
    cudaGetSymbolAddress(&p_asrc,  g_asrc);
    cudaGetSymbolAddress(&p_adst,  g_adst);

    // main stream: zero logits (needed by GEMM epilogue atomics)
    cudaMemsetAsync(p_asrc, 0, (size_t)N * HEADS * sizeof(float));
    cudaMemsetAsync(p_adst, 0, (size_t)N * HEADS * sizeof(float));

    // fork
    cudaEventRecord(evFork, 0);
    cudaStreamWaitEvent(s1, evFork, 0);
    cudaStreamWaitEvent(s2, evFork, 0);

    // s1: CSR build + scalar reductions + small memsets
    cudaMemsetAsync(p_pool, 0, OUTD * sizeof(float), s1);
    cudaMemsetAsync(p_deg,  0, (size_t)N * sizeof(int), s1);
    cudaMemsetAsync(p_scal, 0, sizeof(float), s1);
    k_count<<<(E + 255) / 256, 256, 0, s1>>>(ei, E);
    k_scan<<<1, 1024, 0, s1>>>(N);
    k_fill<<<(ET + 255) / 256, 256, 0, s1>>>(ei, E, N);
    k_easum<<<64, 256, 0, s1>>>(ea, E);
    k_kcoef<<<1, 256, 0, s1>>>(Wedge, att_edge);
    cudaEventRecord(evCSR, s1);

    // s2: weight conversion (coalesced transpose; overlaps cvtA)
    {
        dim3 gw2(OUTD / 32, EMBED / 32);
        k_cvtW<<<gw2, 256, 0, s2>>>(W);
    }
    cudaEventRecord(evW, s2);

    // main: cvtA -> GEMM(+logits) -> agg -> clf
    k_cvtA<<<(PADN * (EMBED / 4) + 255) / 256, 256>>>((const float4*)x, N);
    cudaStreamWaitEvent(0, evW, 0);

    dim3 gg(OUTD / 128, PADN / 128);
    k_gemm_mma<<<gg, 256, SMEM_GEMM>>>(N, att_src, att_dst);

    cudaStreamWaitEvent(0, evCSR, 0);
    k_agg<<<(N * 32 + 255) / 256, 256>>>(N, E, ea, tip, iip);

    k_clf<<<1, 256>>>(bias, tip, iip, clfW, clfb, N, out);
}

// round 10
// speedup vs baseline: 1.0726x; 1.0726x over previous
#include <cuda_runtime.h>
#include <cuda_bf16.h>
#include <cstdint>

#define EMBED 768
#define OUTD  1024
#define HEADS 8
#define HD    128
#define MAXN  10000
#define MAXE  160000
#define MAXET (MAXN + MAXE)
#define PADN  10112            // 79 * 128

// ---------------- scratch ----------------
__device__ float    g_xs[MAXN * OUTD];
__device__ float    g_h[MAXN * OUTD];        // only rows text/image are written
__device__ float    g_asrc[MAXN * HEADS];
__device__ float    g_adst[MAXN * HEADS];
__device__ float    g_edge[MAXET * HEADS];
__device__ float    g_scal[16];              // [0]=sum(ea), [1..8]=k[h]
__device__ float    g_pool[OUTD];
// CSR by dst
__device__ int      g_deg[MAXN];
__device__ int      g_off[MAXN + 1];
__device__ int      g_cur[MAXN];
__device__ unsigned g_csr[MAXET];            // (edge_id << 14) | src
// bf16-split copies for tensor-core GEMM
__device__ __nv_bfloat16 g_Ahi[(size_t)PADN * EMBED];
__device__ __nv_bfloat16 g_Alo[(size_t)PADN * EMBED];
__device__ __nv_bfloat16 g_Whi[(size_t)OUTD * EMBED];   // W^T [n][k]
__device__ __nv_bfloat16 g_Wlo[(size_t)OUTD * EMBED];

// ---------------- PTX helpers ----------------
__device__ __forceinline__ uint32_t smem_u32(const void* p) {
    uint32_t a;
    asm("{ .reg .u64 t; cvta.to.shared.u64 t, %1; cvt.u32.u64 %0, t; }" : "=r"(a) : "l"(p));
    return a;
}
__device__ __forceinline__ void cp16(uint32_t s, const void* g) {
    asm volatile("cp.async.cg.shared.global [%0], [%1], 16;" :: "r"(s), "l"(g));
}
__device__ __forceinline__ void cp_commit() {
    asm volatile("cp.async.commit_group;" ::: "memory");
}
template <int N>
__device__ __forceinline__ void cp_wait() {
    asm volatile("cp.async.wait_group %0;" :: "n"(N) : "memory");
}
__device__ __forceinline__ void ldsm4(uint32_t& r0, uint32_t& r1, uint32_t& r2, uint32_t& r3,
                                      uint32_t addr) {
    asm volatile("ldmatrix.sync.aligned.m8n8.x4.shared.b16 {%0,%1,%2,%3}, [%4];"
                 : "=r"(r0), "=r"(r1), "=r"(r2), "=r"(r3) : "r"(addr));
}
__device__ __forceinline__ void mma16816(float* d, const uint32_t* a, const uint32_t* b) {
    asm volatile(
        "mma.sync.aligned.m16n8k16.row.col.f32.bf16.bf16.f32 "
        "{%0,%1,%2,%3}, {%4,%5,%6,%7}, {%8,%9}, {%0,%1,%2,%3};"
        : "+f"(d[0]), "+f"(d[1]), "+f"(d[2]), "+f"(d[3])
        : "r"(a[0]), "r"(a[1]), "r"(a[2]), "r"(a[3]), "r"(b[0]), "r"(b[1]));
}

__device__ __forceinline__ uint32_t sw_off(int row, int c) {
    return (uint32_t)(row * 64 + ((c ^ ((row >> 1) & 3)) << 4));
}

// ---------------- K0a: split x into bf16 hi/lo (float4 vectorized) ----------------
__global__ void k_cvtA(const float4* __restrict__ x, int N) {
    int i = blockIdx.x * blockDim.x + threadIdx.x;
    if (i >= PADN * (EMBED / 4)) return;
    int row = i / (EMBED / 4);
    float4 v = (row < N) ? x[i] : make_float4(0.f, 0.f, 0.f, 0.f);
    __nv_bfloat16 h0 = __float2bfloat16(v.x), h1 = __float2bfloat16(v.y);
    __nv_bfloat16 h2 = __float2bfloat16(v.z), h3 = __float2bfloat16(v.w);
    __nv_bfloat162* hi = (__nv_bfloat162*)&g_Ahi[(size_t)i * 4];
    __nv_bfloat162* lo = (__nv_bfloat162*)&g_Alo[(size_t)i * 4];
    hi[0] = __nv_bfloat162(h0, h1);
    hi[1] = __nv_bfloat162(h2, h3);
    lo[0] = __nv_bfloat162(__float2bfloat16(v.x - __bfloat162float(h0)),
                           __float2bfloat16(v.y - __bfloat162float(h1)));
    lo[1] = __nv_bfloat162(__float2bfloat16(v.z - __bfloat162float(h2)),
                           __float2bfloat16(v.w - __bfloat162float(h3)));
}

// ---------------- K0b: W^T split via smem tile transpose (coalesced both ways) ----------------
__global__ __launch_bounds__(256)
void k_cvtW(const float* __restrict__ W) {
    __shared__ float tile[32][33];
    const int k0 = blockIdx.y * 32;
    const int n0 = blockIdx.x * 32;
    const int tx = threadIdx.x & 31, ty = threadIdx.x >> 5;
    #pragma unroll
    for (int i = 0; i < 32; i += 8)
        tile[ty + i][tx] = W[(size_t)(k0 + ty + i) * OUTD + n0 + tx];
    __syncthreads();
    #pragma unroll
    for (int i = 0; i < 32; i += 8) {
        float v = tile[tx][ty + i];
        __nv_bfloat16 hi = __float2bfloat16(v);
        __nv_bfloat16 lo = __float2bfloat16(v - __bfloat162float(hi));
        g_Whi[(size_t)(n0 + ty + i) * EMBED + k0 + tx] = hi;
        g_Wlo[(size_t)(n0 + ty + i) * EMBED + k0 + tx] = lo;
    }
}

// ---------------- K2: HMMA bf16-split GEMM + fused attention logits ----------------
#define KCH    32
#define NCHUNK (EMBED / KCH)      // 24
#define TILEB  (128 * 64)
#define STAGEB (4 * TILEB)
#define NSTAGE 3
#define SMEM_GEMM (NSTAGE * STAGEB)

__global__ __launch_bounds__(256, 2)
void k_gemm_mma(int M, const float* __restrict__ att_src,
                const float* __restrict__ att_dst) {
    extern __shared__ char smem[];
    const uint32_t sb = smem_u32(smem);
    const int tid = threadIdx.x;
    const int wid = tid >> 5, lane = tid & 31;
    const int warp_m = wid & 3;
    const int warp_n = wid >> 2;
    const int rowBase = blockIdx.y * 128;
    const int colBase = blockIdx.x * 128;
    const int head = colBase >> 7;

    const __nv_bfloat16* src[4] = {
        g_Ahi + (size_t)rowBase * EMBED,
        g_Alo + (size_t)rowBase * EMBED,
        g_Whi + (size_t)colBase * EMBED,
        g_Wlo + (size_t)colBase * EMBED };

    const int chunk0 = tid * 2;
    const int row0 = chunk0 >> 2, cc0 = chunk0 & 3;
    const int row1 = (chunk0 + 1) >> 2, cc1 = (chunk0 + 1) & 3;
    const uint32_t so0 = sw_off(row0, cc0);
    const uint32_t so1 = sw_off(row1, cc1);

    auto stage_load = [&](int c, int s) {
        const uint32_t base = sb + s * STAGEB;
        const int k0 = c * KCH;
        #pragma unroll
        for (int t = 0; t < 4; t++) {
            const __nv_bfloat16* g = src[t] + k0;
            cp16(base + t * TILEB + so0, g + (size_t)row0 * EMBED + cc0 * 8);
            cp16(base + t * TILEB + so1, g + (size_t)row1 * EMBED + cc1 * 8);
        }
        cp_commit();
    };

    stage_load(0, 0);
    stage_load(1, 1);

    float acc[2][8][4];
    #pragma unroll
    for (int mb = 0; mb < 2; mb++)
        #pragma unroll
        for (int nb = 0; nb < 8; nb++)
            #pragma unroll
            for (int j = 0; j < 4; j++) acc[mb][nb][j] = 0.f;

    const int l_tile = lane >> 3, l_rin = lane & 7;

    for (int c = 0; c < NCHUNK; c++) {
        if (c + 1 < NCHUNK) cp_wait<1>(); else cp_wait<0>();
        __syncthreads();
        if (c + 2 < NCHUNK) stage_load(c + 2, (c + 2) % NSTAGE);

        const uint32_t base = sb + (c % NSTAGE) * STAGEB;
        #pragma unroll
        for (int ks = 0; ks < 2; ks++) {
            uint32_t a[2][2][4];
            uint32_t b[2][8][2];
            #pragma unroll
            for (int v = 0; v < 2; v++)
                #pragma unroll
                for (int mb = 0; mb < 2; mb++) {
                    int r = warp_m * 32 + mb * 16 + ((l_tile & 1) << 3) + l_rin;
                    int cch = ks * 2 + (l_tile >> 1);
                    ldsm4(a[v][mb][0], a[v][mb][1], a[v][mb][2], a[v][mb][3],
                          base + v * TILEB + sw_off(r, cch));
                }
            #pragma unroll
            for (int v = 0; v < 2; v++)
                #pragma unroll
                for (int p = 0; p < 4; p++) {
                    int r = warp_n * 64 + p * 16 + ((l_tile >> 1) << 3) + l_rin;
                    int cch = ks * 2 + (l_tile & 1);
                    ldsm4(b[v][p * 2][0], b[v][p * 2][1],
                          b[v][p * 2 + 1][0], b[v][p * 2 + 1][1],
                          base + (2 + v) * TILEB + sw_off(r, cch));
                }
            #pragma unroll
            for (int mb = 0; mb < 2; mb++)
                #pragma unroll
                for (int nb = 0; nb < 8; nb++) {
                    mma16816(acc[mb][nb], a[0][mb], b[0][nb]);
                    mma16816(acc[mb][nb], a[0][mb], b[1][nb]);
                    mma16816(acc[mb][nb], a[1][mb], b[0][nb]);
                }
        }
        // no trailing sync: next iteration's top __syncthreads (after cp_wait)
        // orders all warps' compute(c) before stage (c+3)%3 is overwritten.
    }

    const int tr = lane >> 2, tc = (lane & 3) * 2;

    float as[16], ad[16];
    #pragma unroll
    for (int nb = 0; nb < 8; nb++)
        #pragma unroll
        for (int j = 0; j < 2; j++) {
            int col = warp_n * 64 + nb * 8 + tc + j;
            as[nb * 2 + j] = att_src[head * HD + col];
            ad[nb * 2 + j] = att_dst[head * HD + col];
        }

    #pragma unroll
    for (int mb = 0; mb < 2; mb++) {
        #pragma unroll
        for (int half = 0; half < 2; half++) {
            int row = rowBase + warp_m * 32 + mb * 16 + half * 8 + tr;
            float ps = 0.f, pd = 0.f;
            #pragma unroll
            for (int nb = 0; nb < 8; nb++)
                #pragma unroll
                for (int j = 0; j < 2; j++) {
                    float v = acc[mb][nb][half * 2 + j];
                    ps += v * as[nb * 2 + j];
                    pd += v * ad[nb * 2 + j];
                }
            #pragma unroll
            for (int o = 1; o < 4; o <<= 1) {
                ps += __shfl_xor_sync(0xffffffffu, ps, o);
                pd += __shfl_xor_sync(0xffffffffu, pd, o);
            }
            if (row < M) {
                if ((lane & 3) == 0) {
                    atomicAdd(&g_asrc[row * HEADS + head], ps);
                    atomicAdd(&g_adst[row * HEADS + head], pd);
                }
                float* dst = &g_xs[(size_t)row * OUTD + colBase + warp_n * 64 + tc];
                #pragma unroll
                for (int nb = 0; nb < 8; nb++) {
                    float2 v = make_float2(acc[mb][nb][half * 2], acc[mb][nb][half * 2 + 1]);
                    *(float2*)(dst + nb * 8) = v;
                }
            }
        }
    }
}

// ---------------- K1a: parallel sum of ea ----------------
__global__ void k_easum(const float* __restrict__ ea, int E) {
    __shared__ float sh[256];
    float s = 0.f;
    for (int i = blockIdx.x * 256 + threadIdx.x; i < E; i += gridDim.x * 256) s += ea[i];
    sh[threadIdx.x] = s; __syncthreads();
    for (int o = 128; o; o >>= 1) {
        if (threadIdx.x < o) sh[threadIdx.x] += sh[threadIdx.x + o];
        __syncthreads();
    }
    if (threadIdx.x == 0) atomicAdd(&g_scal[0], sh[0]);
}

// ---------------- K1b: per-head edge coefficient k[h] ----------------
__global__ void k_kcoef(const float* __restrict__ Wedge,
                        const float* __restrict__ att_edge) {
    int wid = threadIdx.x >> 5, lane = threadIdx.x & 31;
    float s = 0.f;
    for (int c = lane; c < HD; c += 32)
        s += Wedge[wid * HD + c] * att_edge[wid * HD + c];
    #pragma unroll
    for (int o = 16; o; o >>= 1) s += __shfl_down_sync(0xffffffffu, s, o);
    if (lane == 0) g_scal[1 + wid] = s;
}

// ---------------- CSR build ----------------
__global__ void k_count(const int* __restrict__ ei, int E) {
    int e = blockIdx.x * blockDim.x + threadIdx.x;
    if (e < E) atomicAdd(&g_deg[ei[E + e]], 1);
}

__global__ __launch_bounds__(1024)
void k_scan(int N) {
    __shared__ int sh[1024];
    int t = threadIdx.x;
    int chunk = (N + 1023) / 1024;
    int s0 = min(t * chunk, N), s1 = min(s0 + chunk, N);
    int sum = 0;
    for (int n = s0; n < s1; n++) sum += g_deg[n] + 1;
    sh[t] = sum; __syncthreads();
    for (int o = 1; o < 1024; o <<= 1) {
        int v = (t >= o) ? sh[t - o] : 0;
        __syncthreads();
        sh[t] += v;
        __syncthreads();
    }
    int run = (t == 0) ? 0 : sh[t - 1];
    for (int n = s0; n < s1; n++) {
        g_off[n] = run;
        g_cur[n] = run;
        run += g_deg[n] + 1;
    }
    if (t == 1023) g_off[N] = sh[1023];
}

__global__ void k_fill(const int* __restrict__ ei, int E, int N) {
    int t = blockIdx.x * blockDim.x + threadIdx.x;
    if (t >= E + N) return;
    int d, s;
    if (t < E) { d = ei[E + t]; s = ei[t]; }
    else       { d = s = t - E; }
    int pos = atomicAdd(&g_cur[d], 1);
    g_csr[pos] = ((unsigned)t << 14) | (unsigned)s;
}

// ---------------- K4: fused alpha+exp (denom computed in agg) ----------------
__global__ void k_alphaexp(const int* __restrict__ ei, const float* __restrict__ ea,
                           int E, int N) {
    int t = blockIdx.x * blockDim.x + threadIdx.x;
    int total = (E + N) * HEADS;
    if (t >= total) return;
    int e = t >> 3, h = t & 7;
    int s, d; float av;
    if (e < E) { s = ei[e]; d = ei[E + e]; av = ea[e]; }
    else       { s = d = e - E;            av = g_scal[0] / (float)E; }
    float a = g_asrc[s * HEADS + h] + g_adst[d * HEADS + h] + av * g_scal[1 + h];
    a = (a >= 0.f) ? a : 0.2f * a;
    g_edge[t] = __expf(a);
}

// ---------------- K6: CSR agg + in-warp denom + fused mean-pool ----------------
__global__ __launch_bounds__(256)
void k_agg(int N, const int* __restrict__ tip, const int* __restrict__ iip) {
    __shared__ float spool[OUTD];
    const int tid = threadIdx.x;
    for (int j = tid; j < OUTD; j += 256) spool[j] = 0.f;
    __syncthreads();

    int gw = (blockIdx.x * 256 + tid) >> 5;
    int lane = tid & 31;
    if (gw < N) {
        const int st = g_off[gw], en = g_off[gw + 1];

        float4 acc[HEADS];
        float dsum[HEADS];
        #pragma unroll
        for (int h = 0; h < HEADS; h++) {
            acc[h] = make_float4(0.f, 0.f, 0.f, 0.f);
            dsum[h] = 0.f;
        }

        #pragma unroll 2
        for (int i = st; i < en; i++) {
            unsigned p = g_csr[i];
            int e = p >> 14, s = p & 0x3FFF;
            const float4* row = (const float4*)&g_xs[(size_t)s * OUTD];
            const float* we = &g_edge[(size_t)e * HEADS];
            #pragma unroll
            for (int h = 0; h < HEADS; h++) {
                float w = we[h];
                float4 v = row[h * 32 + lane];
                dsum[h] += w;
                acc[h].x += w * v.x;
                acc[h].y += w * v.y;
                acc[h].z += w * v.z;
                acc[h].w += w * v.w;
            }
        }
        #pragma unroll
        for (int h = 0; h < HEADS; h++) {
            float inv = 1.f / dsum[h];
            acc[h].x *= inv; acc[h].y *= inv; acc[h].z *= inv; acc[h].w *= inv;
        }

        #pragma unroll
        for (int h = 0; h < HEADS; h++) {
            float* sp = &spool[h * HD + lane * 4];
            atomicAdd(sp + 0, acc[h].x);
            atomicAdd(sp + 1, acc[h].y);
            atomicAdd(sp + 2, acc[h].z);
            atomicAdd(sp + 3, acc[h].w);
        }

        int t = tip[0], im = iip[0];
        if (gw == t || gw == im) {
            float4* out = (float4*)&g_h[(size_t)gw * OUTD];
            #pragma unroll
            for (int h = 0; h < HEADS; h++) out[h * 32 + lane] = acc[h];
        }
    }
    __syncthreads();
    for (int j = tid; j < OUTD; j += 256) atomicAdd(&g_pool[j], spool[j]);
}

// ---------------- K8: fused vector + classifier ----------------
__global__ void k_clf(const float* __restrict__ bias,
                      const int* __restrict__ tip, const int* __restrict__ iip,
                      const float* __restrict__ clfW, const float* __restrict__ clfb,
                      int N, float* __restrict__ out) {
    __shared__ float s0[256], s1[256];
    int t = threadIdx.x;
    int ti = tip[0], im = iip[0];
    float a0 = 0.f, a1 = 0.f;
    for (int j = t; j < 3 * OUTD; j += 256) {
        int jj = j & (OUTD - 1);
        int seg = j >> 10;
        float b = bias[jj];
        float f;
        if (seg == 0)      f = g_pool[jj] / (float)N + b;
        else if (seg == 1) f = g_h[(size_t)ti * OUTD + jj] + b;
        else               f = g_h[(size_t)im * OUTD + jj] + b;
        a0 += f * clfW[2 * j];
        a1 += f * clfW[2 * j + 1];
    }
    s0[t] = a0; s1[t] = a1; __syncthreads();
    for (int o = 128; o; o >>= 1) {
        if (t < o) { s0[t] += s0[t + o]; s1[t] += s1[t + o]; }
        __syncthreads();
    }
    if (t == 0) {
        out[0] = s0[0] + clfb[0];
        out[1] = s1[0] + clfb[1];
    }
}

// ---------------- launch ----------------
extern "C" void kernel_launch(void* const* d_in, const int* in_sizes, int n_in,
                              void* d_out, int out_size) {
    const float* x        = (const float*)d_in[0];
    const int*   ei       = (const int*)  d_in[1];
    const float* ea       = (const float*)d_in[2];
    const int*   tip      = (const int*)  d_in[3];
    const int*   iip      = (const int*)  d_in[4];
    const float* W        = (const float*)d_in[5];
    const float* att_src  = (const float*)d_in[6];
    const float* att_dst  = (const float*)d_in[7];
    const float* Wedge    = (const float*)d_in[8];
    const float* att_edge = (const float*)d_in[9];
    const float* bias     = (const float*)d_in[10];
    const float* clfW     = (const float*)d_in[11];
    const float* clfb     = (const float*)d_in[12];
    float* out = (float*)d_out;

    int N  = in_sizes[0] / EMBED;
    int E  = in_sizes[1] / 2;
    int ET = E + N;

    static cudaStream_t s1, s2;
    static cudaEvent_t evFork, evCSR, evW;
    static int inited = 0;
    if (!inited) {
        cudaStreamCreateWithFlags(&s1, cudaStreamNonBlocking);
        cudaStreamCreateWithFlags(&s2, cudaStreamNonBlocking);
        cudaEventCreateWithFlags(&evFork, cudaEventDisableTiming);
        cudaEventCreateWithFlags(&evCSR,  cudaEventDisableTiming);
        cudaEventCreateWithFlags(&evW,    cudaEventDisableTiming);
        cudaFuncSetAttribute(k_gemm_mma, cudaFuncAttributeMaxDynamicSharedMemorySize, SMEM_GEMM);
        inited = 1;
    }

    void *p_pool, *p_deg, *p_scal, *p_asrc, *p_adst;
    cudaGetSymbolAddress(&p_pool,  g_pool);
    cudaGetSymbolAddress(&p_deg,   g_deg);
    cudaGetSymbolAddress(&p_scal,  g_scal);
    cudaGetSymbolAddress(&p_asrc,  g_asrc);
    cudaGetSymbolAddress(&p_adst,  g_adst);

    // main stream: zero logits (needed by GEMM epilogue atomics)
    cudaMemsetAsync(p_asrc, 0, (size_t)N * HEADS * sizeof(float));
    cudaMemsetAsync(p_adst, 0, (size_t)N * HEADS * sizeof(float));

    // fork
    cudaEventRecord(evFork, 0);
    cudaStreamWaitEvent(s1, evFork, 0);
    cudaStreamWaitEvent(s2, evFork, 0);

    // s1: CSR build + scalar reductions + small memsets
    cudaMemsetAsync(p_pool, 0, OUTD * sizeof(float), s1);
    cudaMemsetAsync(p_deg,  0, (size_t)N * sizeof(int), s1);
    cudaMemsetAsync(p_scal, 0, sizeof(float), s1);
    k_count<<<(E + 255) / 256, 256, 0, s1>>>(ei, E);
    k_scan<<<1, 1024, 0, s1>>>(N);
    k_fill<<<(ET + 255) / 256, 256, 0, s1>>>(ei, E, N);
    k_easum<<<64, 256, 0, s1>>>(ea, E);
    k_kcoef<<<1, 256, 0, s1>>>(Wedge, att_edge);
    cudaEventRecord(evCSR, s1);

    // s2: weight conversion (coalesced transpose; overlaps cvtA)
    {
        dim3 gw2(OUTD / 32, EMBED / 32);
        k_cvtW<<<gw2, 256, 0, s2>>>(W);
    }
    cudaEventRecord(evW, s2);

    // main: cvtA -> GEMM(+logits) -> alphaexp -> agg -> clf
    k_cvtA<<<(PADN * (EMBED / 4) + 255) / 256, 256>>>((const float4*)x, N);
    cudaStreamWaitEvent(0, evW, 0);

    dim3 gg(OUTD / 128, PADN / 128);
    k_gemm_mma<<<gg, 256, SMEM_GEMM>>>(N, att_src, att_dst);

    cudaStreamWaitEvent(0, evCSR, 0);
    int totalEH = ET * HEADS;
    k_alphaexp<<<(totalEH + 255) / 256, 256>>>(ei, ea, E, N);
    k_agg<<<(N * 32 + 255) / 256, 256>>>(N, tip, iip);

    k_clf<<<1, 256>>>(bias, tip, iip, clfW, clfb, N, out);
}